// round 6
// baseline (speedup 1.0000x reference)
#include <cuda_runtime.h>
#include <cuda_bf16.h>
#include <cfloat>
#include <math.h>

// ---------------------------------------------------------------------------
// GMMNet forward, fused per-tile aggregate+GEMM.
// Per 64-node block: aggregate Y (fp32, smem) -> split to packed bf16 hi/lo
// in place -> 3-product mma GEMM vs preprocessed B -> bias+leakyrelu -> out.
// ---------------------------------------------------------------------------

namespace {
constexpr int N_NODES = 50000;
constexpr int N_EDGES = 800000;
constexpr int H       = 64;
constexpr int KY      = 320;          // 4*64 gaussian + 64 root
constexpr int G_GRAPHS = 50;
constexpr int NBLK_SCAN = (N_NODES + 255) / 256;        // 196
constexpr int SETUP_MAX = 4 * KY * H;                   // 81920 (largest range)
// layer-kernel smem (in u32 words): sY[320][68] + sB[16][68] + bias[64]
constexpr int SY_WORDS  = 320 * 68;
constexpr int SB_WORDS  = 16 * 68;
constexpr int SMEM_WORDS = SY_WORDS + SB_WORDS + 64;
constexpr int SMEM_BYTES = SMEM_WORDS * 4;              // ~91.7 KB
}

// -------------------- device scratch (static, no allocs) -------------------
__device__ unsigned g_Bp[4 * KY * H];                  // packed hi<<16|lo
__device__ float    g_gwall[(size_t)4 * N_EDGES * 4];  // per-layer, CSR order
__device__ float2   g_eacsr[N_EDGES];                  // edge_attr in CSR order
__device__ int      g_srccsr[N_EDGES];                 // src in CSR order
__device__ float g_x0[(size_t)N_NODES * H];
__device__ float g_x1[(size_t)N_NODES * H];
__device__ float g_x2[(size_t)N_NODES * H];
__device__ float g_x3[(size_t)N_NODES * H];
__device__ float g_x4[(size_t)N_NODES * H];
__device__ int   g_deg[N_NODES];
__device__ int   g_rowptr[N_NODES + 1];
__device__ int   g_cursor[N_NODES];
__device__ int   g_part[256];
__device__ unsigned g_pmax[G_GRAPHS * 256];

// -------------------- helpers ----------------------------------------------
__device__ __forceinline__ unsigned fenc(float f) {
    unsigned u = __float_as_uint(f);
    return (u & 0x80000000u) ? ~u : (u | 0x80000000u);
}
__device__ __forceinline__ float fdec(unsigned u) {
    unsigned v = (u & 0x80000000u) ? (u ^ 0x80000000u) : ~u;
    return __uint_as_float(v);
}
__device__ __forceinline__ unsigned pack_split(float v) {
    __nv_bfloat16 h = __float2bfloat16_rn(v);
    __nv_bfloat16 l = __float2bfloat16_rn(v - __bfloat162float(h));
    unsigned hu = __bfloat16_as_ushort(h), lu = __bfloat16_as_ushort(l);
    return (hu << 16) | lu;
}
__device__ __forceinline__ void mma_bf16(float* d, const unsigned* a, const unsigned* b) {
    asm volatile(
        "mma.sync.aligned.m16n8k16.row.col.f32.bf16.bf16.f32 "
        "{%0,%1,%2,%3}, {%4,%5,%6,%7}, {%8,%9}, {%0,%1,%2,%3};\n"
        : "+f"(d[0]), "+f"(d[1]), "+f"(d[2]), "+f"(d[3])
        : "r"(a[0]), "r"(a[1]), "r"(a[2]), "r"(a[3]),
          "r"(b[0]), "r"(b[1]));
}

// -------------------- setup: zero deg/pmax + split-pack B ------------------
// B[l][j][h]: j<256 -> g_l[(j&63)*256 + (j>>6)*64 + h]; else rw_l[(j-256)*64+h]
__global__ void k_setup(const float* g0, const float* r0,
                        const float* g1, const float* r1,
                        const float* g2, const float* r2,
                        const float* g3, const float* r3) {
    int idx = blockIdx.x * blockDim.x + threadIdx.x;
    if (idx < N_NODES) g_deg[idx] = 0;
    if (idx < G_GRAPHS * 256) g_pmax[idx] = 0u;
    if (idx < 4 * KY * H) {
        int l = idx / (KY * H);
        int rem = idx % (KY * H);
        int j = rem / H, h = rem % H;
        const float* gW = (l == 0) ? g0 : (l == 1) ? g1 : (l == 2) ? g2 : g3;
        const float* rw = (l == 0) ? r0 : (l == 1) ? r1 : (l == 2) ? r2 : r3;
        float v = (j < 256) ? gW[(size_t)(j & 63) * 256 + (j >> 6) * 64 + h]
                            : rw[(size_t)(j - 256) * 64 + h];
        g_Bp[idx] = pack_split(v);
    }
}

// -------------------- CSR build --------------------------------------------
__global__ void k_hist(const int* __restrict__ ei) {
    int e = blockIdx.x * blockDim.x + threadIdx.x;
    if (e < N_EDGES) atomicAdd(&g_deg[ei[N_EDGES + e]], 1);
}

__global__ void k_scan_part() {
    __shared__ int s[256];
    int i = blockIdx.x * 256 + threadIdx.x;
    s[threadIdx.x] = (i < N_NODES) ? g_deg[i] : 0;
    __syncthreads();
    for (int o = 128; o > 0; o >>= 1) {
        if (threadIdx.x < o) s[threadIdx.x] += s[threadIdx.x + o];
        __syncthreads();
    }
    if (threadIdx.x == 0) g_part[blockIdx.x] = s[0];
}

__global__ void k_scan_final() {
    __shared__ int red[256];
    __shared__ int s[256];
    __shared__ int prefix;
    int t = threadIdx.x;
    // exclusive prefix over block sums: sum of g_part[0..bid)
    red[t] = (t < NBLK_SCAN && t < blockIdx.x) ? g_part[t] : 0;
    __syncthreads();
    for (int o = 128; o > 0; o >>= 1) {
        if (t < o) red[t] += red[t + o];
        __syncthreads();
    }
    if (t == 0) prefix = red[0];
    int i = blockIdx.x * 256 + t;
    int d = (i < N_NODES) ? g_deg[i] : 0;
    s[t] = d;
    __syncthreads();
    for (int o = 1; o < 256; o <<= 1) {
        int v = (t >= o) ? s[t - o] : 0;
        __syncthreads();
        s[t] += v;
        __syncthreads();
    }
    if (i < N_NODES) {
        int excl = prefix + s[t] - d;
        g_rowptr[i] = excl;
        g_cursor[i] = excl;
    }
    if (i == 0) g_rowptr[N_NODES] = N_EDGES;
}

__global__ void k_scatter(const int* __restrict__ ei, const float* __restrict__ ea) {
    int e = blockIdx.x * blockDim.x + threadIdx.x;
    if (e < N_EDGES) {
        int srcn = ei[e];
        int dstn = ei[N_EDGES + e];
        int pos = atomicAdd(&g_cursor[dstn], 1);
        g_srccsr[pos] = srcn;
        g_eacsr[pos] = make_float2(ea[2 * e], ea[2 * e + 1]);
    }
}

// -------------------- all-layer Gaussian edge weights (CSR order) ----------
__global__ void k_gw_all(const float* m0, const float* s0,
                         const float* m1, const float* s1,
                         const float* m2, const float* s2,
                         const float* m3, const float* s3) {
    int i = blockIdx.x * blockDim.x + threadIdx.x;
    if (i >= N_EDGES) return;
    float2 e2 = g_eacsr[i];
    const float* mus[4] = {m0, m1, m2, m3};
    const float* sgs[4] = {s0, s1, s2, s3};
#pragma unroll
    for (int l = 0; l < 4; l++) {
        float4 o;
        float* op = &o.x;
#pragma unroll
        for (int k = 0; k < 4; k++) {
            float mm0 = __ldg(mus[l] + 2 * k), mm1 = __ldg(mus[l] + 2 * k + 1);
            float ss0 = __ldg(sgs[l] + 2 * k), ss1 = __ldg(sgs[l] + 2 * k + 1);
            float d0 = e2.x - mm0, d1 = e2.y - mm1;
            float tt = d0 * d0 / (1e-15f + ss0 * ss0) + d1 * d1 / (1e-15f + ss1 * ss1);
            op[k] = expf(-0.5f * tt);
        }
        *reinterpret_cast<float4*>(&g_gwall[(size_t)l * N_EDGES * 4 + (size_t)4 * i]) = o;
    }
}

// -------------------- fused layer: aggregate + GEMM ------------------------
// Block = 64 nodes, 256 threads (8 warps).
__global__ __launch_bounds__(256) void k_layer(const float* __restrict__ xin,
                                               const float* __restrict__ gw,
                                               const unsigned* __restrict__ Bp,
                                               const float* __restrict__ bias,
                                               float* __restrict__ C,
                                               const float* __restrict__ resid_in,
                                               float* __restrict__ resid_out) {
    extern __shared__ unsigned smem_u[];
    unsigned* sY = smem_u;                     // [col 320][node 68-pad]
    float*    sYf = reinterpret_cast<float*>(sY);
    unsigned* sB = sY + SY_WORDS;              // [k 16][n 68-pad]
    float*    sBias = reinterpret_cast<float*>(sB + SB_WORDS);

    const int tid = threadIdx.x;
    const int w = tid >> 5, lane = tid & 31;
    const int bm = blockIdx.x * 64;
    if (tid < 64) sBias[tid] = bias[tid];

    // ---------------- Phase A: aggregate 8 nodes per warp ------------------
    const int nbase = bm + w * 8;
#pragma unroll 1
    for (int j = 0; j < 8; j++) {
        int n = nbase + j;
        if (n >= N_NODES) break;
        int s = g_rowptr[n], e = g_rowptr[n + 1];
        float a[8];
#pragma unroll
        for (int i = 0; i < 8; i++) a[i] = 0.f;
#pragma unroll 2
        for (int i = s; i < e; i++) {
            int src = __ldg(&g_srccsr[i]);
            float4 g4 = *reinterpret_cast<const float4*>(gw + (size_t)4 * i);
            const float* p = xin + (size_t)src * 64 + lane;
            float x0 = __ldg(p), x1 = __ldg(p + 32);
            a[0] = fmaf(g4.x, x0, a[0]);  a[1] = fmaf(g4.x, x1, a[1]);
            a[2] = fmaf(g4.y, x0, a[2]);  a[3] = fmaf(g4.y, x1, a[3]);
            a[4] = fmaf(g4.z, x0, a[4]);  a[5] = fmaf(g4.z, x1, a[5]);
            a[6] = fmaf(g4.w, x0, a[6]);  a[7] = fmaf(g4.w, x1, a[7]);
        }
        float inv = (e > s) ? 1.0f / (float)(e - s) : 1.0f;
        int nl = w * 8 + j;
#pragma unroll
        for (int k = 0; k < 4; k++) {
            sYf[(k * 64 + lane) * 68 + nl]      = a[2 * k]     * inv;
            sYf[(k * 64 + 32 + lane) * 68 + nl] = a[2 * k + 1] * inv;
        }
        sYf[(256 + lane) * 68 + nl]      = __ldg(xin + (size_t)n * 64 + lane);
        sYf[(256 + 32 + lane) * 68 + nl] = __ldg(xin + (size_t)n * 64 + 32 + lane);
    }
    __syncthreads();

    // ---------------- Convert in place: fp32 -> packed bf16 hi/lo ----------
#pragma unroll
    for (int r = 0; r < 80; r++) {               // 64*320/256 = 80
        int idx = tid + r * 256;
        int nl = idx & 63, col = idx >> 6;
        int addr = col * 68 + nl;
        sY[addr] = pack_split(sYf[addr]);
    }

    // ---------------- Phase B: GEMM (M=64, N=64, K=320) --------------------
    // warps: wm = (w&3)*16, wn = (w>>2)*32; warp tile 16x32 (4 n-tiles of 8)
    const int wm = (w & 3) * 16, wn = (w >> 2) * 32;
    const int g = lane >> 2, tig = lane & 3;

    float acc[4][4];
#pragma unroll
    for (int nt = 0; nt < 4; nt++)
#pragma unroll
        for (int i = 0; i < 4; i++) acc[nt][i] = 0.f;

#pragma unroll 1
    for (int ck = 0; ck < 20; ck++) {
        __syncthreads();
        // stream B chunk [16][64] -> smem
        const unsigned* Bg = Bp + ck * 16 * 64;
#pragma unroll
        for (int r = 0; r < 4; r++) {
            int idx = tid + r * 256;
            int kl = idx >> 6, nn = idx & 63;
            sB[kl * 68 + nn] = Bg[idx];
        }
        __syncthreads();

        int kb = ck * 16;
        // A fragments (row g / g+8 of warp m-strip, k pairs)
        unsigned s00 = sY[(kb + 2 * tig)     * 68 + wm + g];
        unsigned s01 = sY[(kb + 2 * tig + 1) * 68 + wm + g];
        unsigned s10 = sY[(kb + 2 * tig)     * 68 + wm + g + 8];
        unsigned s11 = sY[(kb + 2 * tig + 1) * 68 + wm + g + 8];
        unsigned s02 = sY[(kb + 8 + 2 * tig)     * 68 + wm + g];
        unsigned s03 = sY[(kb + 8 + 2 * tig + 1) * 68 + wm + g];
        unsigned s12 = sY[(kb + 8 + 2 * tig)     * 68 + wm + g + 8];
        unsigned s13 = sY[(kb + 8 + 2 * tig + 1) * 68 + wm + g + 8];
        unsigned ah[4], al[4];
        ah[0] = __byte_perm(s00, s01, 0x7632);  al[0] = __byte_perm(s00, s01, 0x5410);
        ah[1] = __byte_perm(s10, s11, 0x7632);  al[1] = __byte_perm(s10, s11, 0x5410);
        ah[2] = __byte_perm(s02, s03, 0x7632);  al[2] = __byte_perm(s02, s03, 0x5410);
        ah[3] = __byte_perm(s12, s13, 0x7632);  al[3] = __byte_perm(s12, s13, 0x5410);

#pragma unroll
        for (int nt = 0; nt < 4; nt++) {
            int cc = wn + nt * 8 + g;
            unsigned t0 = sB[(2 * tig)     * 68 + cc];
            unsigned t1 = sB[(2 * tig + 1) * 68 + cc];
            unsigned t2 = sB[(8 + 2 * tig)     * 68 + cc];
            unsigned t3 = sB[(8 + 2 * tig + 1) * 68 + cc];
            unsigned bh[2], bl[2];
            bh[0] = __byte_perm(t0, t1, 0x7632);  bl[0] = __byte_perm(t0, t1, 0x5410);
            bh[1] = __byte_perm(t2, t3, 0x7632);  bl[1] = __byte_perm(t2, t3, 0x5410);
            mma_bf16(acc[nt], ah, bh);
            mma_bf16(acc[nt], ah, bl);
            mma_bf16(acc[nt], al, bh);
        }
    }

    // ---------------- epilogue: bias + leakyrelu (+residual) ---------------
#pragma unroll
    for (int nt = 0; nt < 4; nt++) {
        int col = wn + nt * 8 + tig * 2;
        float b0 = sBias[col], b1 = sBias[col + 1];
#pragma unroll
        for (int half = 0; half < 2; half++) {
            int row = bm + wm + g + half * 8;
            if (row < N_NODES) {
                float v0 = acc[nt][2 * half]     + b0;
                float v1 = acc[nt][2 * half + 1] + b1;
                float2 o;
                o.x = v0 > 0.f ? v0 : 0.01f * v0;
                o.y = v1 > 0.f ? v1 : 0.01f * v1;
                *reinterpret_cast<float2*>(C + (size_t)row * 64 + col) = o;
                if (resid_out) {
                    float2 r2 = *reinterpret_cast<const float2*>(
                                    resid_in + (size_t)row * 64 + col);
                    float2 q;
                    q.x = o.x + r2.x;
                    q.y = o.y + r2.y;
                    *reinterpret_cast<float2*>(resid_out + (size_t)row * 64 + col) = q;
                }
            }
        }
    }
}

// -------------------- pooling ----------------------------------------------
__global__ void k_pool(const int* __restrict__ batch) {
    int f = threadIdx.x;
    int n0 = blockIdx.x * 64;
    int n1 = min(n0 + 64, N_NODES);
    const float* base = (f < 64) ? g_x4 : (f < 128) ? g_x1 : (f < 192) ? g_x2 : g_x3;
    int fo = f & 63;
    float m = -FLT_MAX;
    int cur = -1;
    for (int n = n0; n < n1; n++) {
        int b = batch[n];
        if (b != cur) {
            if (cur >= 0) atomicMax(&g_pmax[cur * 256 + f], fenc(m));
            cur = b;
            m = -FLT_MAX;
        }
        m = fmaxf(m, base[(size_t)n * 64 + fo]);
    }
    if (cur >= 0) atomicMax(&g_pmax[cur * 256 + f], fenc(m));
}

// -------------------- final MLP --------------------------------------------
__global__ void k_mlp(const float* __restrict__ w1, const float* __restrict__ b1,
                      const float* __restrict__ gamma, const float* __restrict__ beta,
                      const float* __restrict__ w2, const float* __restrict__ b2,
                      float* __restrict__ out) {
    int g = blockIdx.x;
    int t = threadIdx.x;
    __shared__ float sp[256];
    __shared__ float sz[64];
    for (int i = t; i < 256; i += 64) sp[i] = fdec(g_pmax[g * 256 + i]);
    __syncthreads();
    float acc = b1[t];
    for (int j = 0; j < 256; j++) acc = fmaf(sp[j], w1[j * 64 + t], acc);
    const float invs = 0.99999500003749969f;   // 1/sqrt(1 + 1e-5)
    acc = acc * invs * gamma[t] + beta[t];
    acc = fmaxf(acc, 0.f);
    sz[t] = acc;
    __syncthreads();
    if (t < 10) {
        float o = b2[t];
        for (int j = 0; j < 64; j++) o = fmaf(sz[j], w2[j * 10 + t], o);
        out[g * 10 + t] = o;
    }
}

// -------------------- host launch ------------------------------------------
extern "C" void kernel_launch(void* const* d_in, const int* in_sizes, int n_in,
                              void* d_out, int out_size) {
    (void)in_sizes; (void)n_in; (void)out_size;

    const float* x     = (const float*)d_in[0];
    const int*   ei    = (const int*)d_in[1];
    const int*   batch = (const int*)d_in[2];
    const float* ea    = (const float*)d_in[3];
    const float* g_w[4]   = {(const float*)d_in[4],  (const float*)d_in[9],
                             (const float*)d_in[14], (const float*)d_in[19]};
    const float* mu_w[4]  = {(const float*)d_in[5],  (const float*)d_in[10],
                             (const float*)d_in[15], (const float*)d_in[20]};
    const float* sig_w[4] = {(const float*)d_in[6],  (const float*)d_in[11],
                             (const float*)d_in[16], (const float*)d_in[21]};
    const float* rw_w[4]  = {(const float*)d_in[7],  (const float*)d_in[12],
                             (const float*)d_in[17], (const float*)d_in[22]};
    const float* b_w[4]   = {(const float*)d_in[8],  (const float*)d_in[13],
                             (const float*)d_in[18], (const float*)d_in[23]};
    const float* w1    = (const float*)d_in[24];
    const float* b1    = (const float*)d_in[25];
    const float* gamma = (const float*)d_in[26];
    const float* beta  = (const float*)d_in[27];
    const float* w2    = (const float*)d_in[28];
    const float* b2    = (const float*)d_in[29];

    static bool attr_done = false;
    if (!attr_done) {
        cudaFuncSetAttribute(k_layer, cudaFuncAttributeMaxDynamicSharedMemorySize,
                             SMEM_BYTES);
        attr_done = true;
    }

    float *p_x0, *p_x1, *p_x2, *p_x3, *p_x4;
    unsigned* p_Bp;
    float* p_gw;
    cudaGetSymbolAddress((void**)&p_x0, g_x0);
    cudaGetSymbolAddress((void**)&p_x1, g_x1);
    cudaGetSymbolAddress((void**)&p_x2, g_x2);
    cudaGetSymbolAddress((void**)&p_x3, g_x3);
    cudaGetSymbolAddress((void**)&p_x4, g_x4);
    cudaGetSymbolAddress((void**)&p_Bp, g_Bp);
    cudaGetSymbolAddress((void**)&p_gw, g_gwall);

    const int EB = (N_EDGES + 255) / 256;   // 3125

    k_setup<<<(SETUP_MAX + 255) / 256, 256>>>(g_w[0], rw_w[0], g_w[1], rw_w[1],
                                              g_w[2], rw_w[2], g_w[3], rw_w[3]);
    k_hist<<<EB, 256>>>(ei);
    k_scan_part<<<NBLK_SCAN, 256>>>();
    k_scan_final<<<NBLK_SCAN, 256>>>();
    k_scatter<<<EB, 256>>>(ei, ea);
    k_gw_all<<<EB, 256>>>(mu_w[0], sig_w[0], mu_w[1], sig_w[1],
                          mu_w[2], sig_w[2], mu_w[3], sig_w[3]);

    const int layer_blocks = (N_NODES + 63) / 64;   // 782
    const float* layer_in[4]  = {x, p_x0, p_x1, p_x3};
    float*       layer_out[4] = {p_x0, p_x1, p_x2, p_x4};

    for (int l = 0; l < 4; l++) {
        const float* rin  = (l == 2) ? p_x0 : nullptr;
        float*       rout = (l == 2) ? p_x3 : nullptr;
        k_layer<<<layer_blocks, 256, SMEM_BYTES>>>(
            layer_in[l], p_gw + (size_t)l * N_EDGES * 4,
            p_Bp + (size_t)l * KY * H, b_w[l], layer_out[l], rin, rout);
    }

    k_pool<<<(N_NODES + 63) / 64, 256>>>(batch);
    k_mlp<<<G_GRAPHS, 64>>>(w1, b1, gamma, beta, w2, b2, (float*)d_out);
}

// round 7
// speedup vs baseline: 1.6263x; 1.6263x over previous
#include <cuda_runtime.h>
#include <cuda_bf16.h>
#include <cfloat>
#include <math.h>

// ---------------------------------------------------------------------------
// GMMNet forward: aggregate-then-transform, packed bf16 hi/lo split GEMM.
//   Y[dst, k*64+f] = invdeg(dst) * sum_{e->dst} gw[e,k] * x_in[src,f]
//   Y[dst, 256+f]  = x_in[dst, f]
//   out = leakyrelu( Y @ B + b );  Y, B packed u32 = bf16(hi)<<16 | bf16(lo)
// Separate agg (warp/node, full occupancy) and mma GEMM kernels.
// ---------------------------------------------------------------------------

namespace {
constexpr int N_NODES = 50000;
constexpr int N_EDGES = 800000;
constexpr int H       = 64;
constexpr int KY      = 320;
constexpr int G_GRAPHS = 50;
constexpr int NBLK_SCAN = (N_NODES + 255) / 256;   // 196
constexpr int SETUP_MAX = 4 * KY * H;              // 81920
}

// -------------------- device scratch (static, no allocs) -------------------
__device__ unsigned g_Yp[(size_t)N_NODES * KY];        // 64 MB packed
__device__ unsigned g_Bp[4 * KY * H];                  // packed weights
__device__ float    g_gwall[(size_t)4 * N_EDGES * 4];  // per-layer, CSR order
__device__ float2   g_eacsr[N_EDGES];
__device__ int      g_srccsr[N_EDGES];
__device__ float g_x0[(size_t)N_NODES * H];
__device__ float g_x1[(size_t)N_NODES * H];
__device__ float g_x2[(size_t)N_NODES * H];
__device__ float g_x3[(size_t)N_NODES * H];
__device__ float g_x4[(size_t)N_NODES * H];
__device__ int   g_deg[N_NODES];
__device__ int   g_rowptr[N_NODES + 1];
__device__ int   g_cursor[N_NODES];
__device__ int   g_part[256];
__device__ unsigned g_pmax[G_GRAPHS * 256];

// -------------------- helpers ----------------------------------------------
__device__ __forceinline__ unsigned fenc(float f) {
    unsigned u = __float_as_uint(f);
    return (u & 0x80000000u) ? ~u : (u | 0x80000000u);
}
__device__ __forceinline__ float fdec(unsigned u) {
    unsigned v = (u & 0x80000000u) ? (u ^ 0x80000000u) : ~u;
    return __uint_as_float(v);
}
__device__ __forceinline__ unsigned pack_split(float v) {
    __nv_bfloat16 h = __float2bfloat16_rn(v);
    __nv_bfloat16 l = __float2bfloat16_rn(v - __bfloat162float(h));
    unsigned hu = __bfloat16_as_ushort(h), lu = __bfloat16_as_ushort(l);
    return (hu << 16) | lu;
}
__device__ __forceinline__ void mma_bf16(float* d, const unsigned* a, const unsigned* b) {
    asm volatile(
        "mma.sync.aligned.m16n8k16.row.col.f32.bf16.bf16.f32 "
        "{%0,%1,%2,%3}, {%4,%5,%6,%7}, {%8,%9}, {%0,%1,%2,%3};\n"
        : "+f"(d[0]), "+f"(d[1]), "+f"(d[2]), "+f"(d[3])
        : "r"(a[0]), "r"(a[1]), "r"(a[2]), "r"(a[3]),
          "r"(b[0]), "r"(b[1]));
}

// -------------------- setup: zero deg/pmax + split-pack B ------------------
__global__ void k_setup(const float* g0, const float* r0,
                        const float* g1, const float* r1,
                        const float* g2, const float* r2,
                        const float* g3, const float* r3) {
    int idx = blockIdx.x * blockDim.x + threadIdx.x;
    if (idx < N_NODES) g_deg[idx] = 0;
    if (idx < G_GRAPHS * 256) g_pmax[idx] = 0u;
    if (idx < 4 * KY * H) {
        int l = idx / (KY * H);
        int rem = idx % (KY * H);
        int j = rem / H, h = rem % H;
        const float* gW = (l == 0) ? g0 : (l == 1) ? g1 : (l == 2) ? g2 : g3;
        const float* rw = (l == 0) ? r0 : (l == 1) ? r1 : (l == 2) ? r2 : r3;
        float v = (j < 256) ? gW[(size_t)(j & 63) * 256 + (j >> 6) * 64 + h]
                            : rw[(size_t)(j - 256) * 64 + h];
        g_Bp[idx] = pack_split(v);
    }
}

// -------------------- CSR build --------------------------------------------
__global__ void k_hist(const int* __restrict__ ei) {
    int e = blockIdx.x * blockDim.x + threadIdx.x;
    if (e < N_EDGES) atomicAdd(&g_deg[ei[N_EDGES + e]], 1);
}

__global__ void k_scan_part() {
    __shared__ int s[256];
    int i = blockIdx.x * 256 + threadIdx.x;
    s[threadIdx.x] = (i < N_NODES) ? g_deg[i] : 0;
    __syncthreads();
    for (int o = 128; o > 0; o >>= 1) {
        if (threadIdx.x < o) s[threadIdx.x] += s[threadIdx.x + o];
        __syncthreads();
    }
    if (threadIdx.x == 0) g_part[blockIdx.x] = s[0];
}

__global__ void k_scan_final() {
    __shared__ int red[256];
    __shared__ int s[256];
    __shared__ int prefix;
    int t = threadIdx.x;
    red[t] = (t < NBLK_SCAN && t < blockIdx.x) ? g_part[t] : 0;
    __syncthreads();
    for (int o = 128; o > 0; o >>= 1) {
        if (t < o) red[t] += red[t + o];
        __syncthreads();
    }
    if (t == 0) prefix = red[0];
    int i = blockIdx.x * 256 + t;
    int d = (i < N_NODES) ? g_deg[i] : 0;
    s[t] = d;
    __syncthreads();
    for (int o = 1; o < 256; o <<= 1) {
        int v = (t >= o) ? s[t - o] : 0;
        __syncthreads();
        s[t] += v;
        __syncthreads();
    }
    if (i < N_NODES) {
        int excl = prefix + s[t] - d;
        g_rowptr[i] = excl;
        g_cursor[i] = excl;
    }
    if (i == 0) g_rowptr[N_NODES] = N_EDGES;
}

__global__ void k_scatter(const int* __restrict__ ei, const float* __restrict__ ea) {
    int e = blockIdx.x * blockDim.x + threadIdx.x;
    if (e < N_EDGES) {
        int srcn = ei[e];
        int dstn = ei[N_EDGES + e];
        int pos = atomicAdd(&g_cursor[dstn], 1);
        g_srccsr[pos] = srcn;
        g_eacsr[pos] = make_float2(ea[2 * e], ea[2 * e + 1]);
    }
}

// -------------------- all-layer Gaussian edge weights (CSR order) ----------
__global__ void k_gw_all(const float* m0, const float* s0,
                         const float* m1, const float* s1,
                         const float* m2, const float* s2,
                         const float* m3, const float* s3) {
    int i = blockIdx.x * blockDim.x + threadIdx.x;
    if (i >= N_EDGES) return;
    float2 e2 = g_eacsr[i];
    const float* mus[4] = {m0, m1, m2, m3};
    const float* sgs[4] = {s0, s1, s2, s3};
#pragma unroll
    for (int l = 0; l < 4; l++) {
        float4 o;
        float* op = &o.x;
#pragma unroll
        for (int k = 0; k < 4; k++) {
            float mm0 = __ldg(mus[l] + 2 * k), mm1 = __ldg(mus[l] + 2 * k + 1);
            float ss0 = __ldg(sgs[l] + 2 * k), ss1 = __ldg(sgs[l] + 2 * k + 1);
            float d0 = e2.x - mm0, d1 = e2.y - mm1;
            float tt = d0 * d0 / (1e-15f + ss0 * ss0) + d1 * d1 / (1e-15f + ss1 * ss1);
            op[k] = expf(-0.5f * tt);
        }
        *reinterpret_cast<float4*>(&g_gwall[(size_t)l * N_EDGES * 4 + (size_t)4 * i]) = o;
    }
}

// -------------------- aggregation into packed Y: warp per node -------------
__global__ void k_aggY(const float* __restrict__ xin, const float* __restrict__ gw) {
    int w = (blockIdx.x * blockDim.x + threadIdx.x) >> 5;
    int lane = threadIdx.x & 31;
    if (w >= N_NODES) return;
    int s = g_rowptr[w], e = g_rowptr[w + 1];
    float a[8];
#pragma unroll
    for (int i = 0; i < 8; i++) a[i] = 0.f;
#pragma unroll 2
    for (int i = s; i < e; i++) {
        int src = __ldg(&g_srccsr[i]);
        float4 g4 = *reinterpret_cast<const float4*>(gw + (size_t)4 * i);
        const float* p = xin + (size_t)src * 64 + lane;
        float x0 = __ldg(p), x1 = __ldg(p + 32);
        a[0] = fmaf(g4.x, x0, a[0]);  a[1] = fmaf(g4.x, x1, a[1]);
        a[2] = fmaf(g4.y, x0, a[2]);  a[3] = fmaf(g4.y, x1, a[3]);
        a[4] = fmaf(g4.z, x0, a[4]);  a[5] = fmaf(g4.z, x1, a[5]);
        a[6] = fmaf(g4.w, x0, a[6]);  a[7] = fmaf(g4.w, x1, a[7]);
    }
    float inv = (e > s) ? 1.0f / (float)(e - s) : 1.0f;
    unsigned* yo = g_Yp + (size_t)w * KY;
#pragma unroll
    for (int k = 0; k < 4; k++) {
        yo[k * 64 + lane]      = pack_split(a[2 * k]     * inv);
        yo[k * 64 + 32 + lane] = pack_split(a[2 * k + 1] * inv);
    }
    yo[256 + lane]      = pack_split(__ldg(xin + (size_t)w * 64 + lane));
    yo[256 + 32 + lane] = pack_split(__ldg(xin + (size_t)w * 64 + 32 + lane));
}

// -------------------- tensor-core GEMM: out = lrelu(Y @ B + bias) ----------
// Block tile M=128, N=64; K in 10 chunks of 32.
// smem transposed [k][row] stride 132 / [k][n] stride 68 -> conflict-free
// fragment loads (bank = 8t + g + const).
__global__ __launch_bounds__(256) void k_gemm(const unsigned* __restrict__ Bp,
                                              const float* __restrict__ bias,
                                              float* __restrict__ C,
                                              const float* __restrict__ resid_in,
                                              float* __restrict__ resid_out) {
    __shared__ unsigned sA[32 * 132];   // [k][row], pad 132
    __shared__ unsigned sB[32 * 68];    // [k][n],   pad 68
    __shared__ float sBias[64];

    const int tid = threadIdx.x;
    const int bm = blockIdx.x * 128;
    if (tid < 64) sBias[tid] = bias[tid];

    const int w = tid >> 5, lane = tid & 31;
    const int wm = (w & 3) * 32, wn = (w >> 2) * 32;
    const int g = lane >> 2, tig = lane & 3;

    float acc[2][4][4];
#pragma unroll
    for (int mt = 0; mt < 2; mt++)
#pragma unroll
        for (int nt = 0; nt < 4; nt++)
#pragma unroll
            for (int i = 0; i < 4; i++) acc[mt][nt][i] = 0.f;

#pragma unroll 1
    for (int ck = 0; ck < 10; ck++) {
        int k0 = ck * 32;
        __syncthreads();
        // A chunk: rows bm..bm+127, k0..k0+31 -> transposed smem [k][row]
#pragma unroll
        for (int i = 0; i < 4; i++) {
            int idx = tid + i * 256;          // 0..1023
            int r = idx >> 3, q = idx & 7;    // row 0..127, q: 4-k group
            uint4 v = make_uint4(0, 0, 0, 0);
            if (bm + r < N_NODES)
                v = *reinterpret_cast<const uint4*>(
                        g_Yp + (size_t)(bm + r) * KY + k0 + q * 4);
            sA[(q * 4 + 0) * 132 + r] = v.x;
            sA[(q * 4 + 1) * 132 + r] = v.y;
            sA[(q * 4 + 2) * 132 + r] = v.z;
            sA[(q * 4 + 3) * 132 + r] = v.w;
        }
        // B chunk: [k0..k0+31][64]
        const unsigned* Bg = Bp + k0 * 64;
#pragma unroll
        for (int i = 0; i < 8; i++) {
            int idx = tid + i * 256;          // 0..2047
            int kl = idx >> 6, nn = idx & 63;
            sB[kl * 68 + nn] = Bg[idx];
        }
        __syncthreads();

#pragma unroll
        for (int ks = 0; ks < 2; ks++) {
            int kb = ks * 16;
            unsigned ah[2][4], al[2][4];
#pragma unroll
            for (int mt = 0; mt < 2; mt++) {
                int rm = wm + mt * 16;
                unsigned s00 = sA[(kb + 2 * tig)     * 132 + rm + g];
                unsigned s01 = sA[(kb + 2 * tig + 1) * 132 + rm + g];
                unsigned s10 = sA[(kb + 2 * tig)     * 132 + rm + g + 8];
                unsigned s11 = sA[(kb + 2 * tig + 1) * 132 + rm + g + 8];
                unsigned s02 = sA[(kb + 8 + 2 * tig)     * 132 + rm + g];
                unsigned s03 = sA[(kb + 8 + 2 * tig + 1) * 132 + rm + g];
                unsigned s12 = sA[(kb + 8 + 2 * tig)     * 132 + rm + g + 8];
                unsigned s13 = sA[(kb + 8 + 2 * tig + 1) * 132 + rm + g + 8];
                ah[mt][0] = __byte_perm(s00, s01, 0x7632);
                al[mt][0] = __byte_perm(s00, s01, 0x5410);
                ah[mt][1] = __byte_perm(s10, s11, 0x7632);
                al[mt][1] = __byte_perm(s10, s11, 0x5410);
                ah[mt][2] = __byte_perm(s02, s03, 0x7632);
                al[mt][2] = __byte_perm(s02, s03, 0x5410);
                ah[mt][3] = __byte_perm(s12, s13, 0x7632);
                al[mt][3] = __byte_perm(s12, s13, 0x5410);
            }
#pragma unroll
            for (int nt = 0; nt < 4; nt++) {
                int cc = wn + nt * 8 + g;
                unsigned t0 = sB[(kb + 2 * tig)     * 68 + cc];
                unsigned t1 = sB[(kb + 2 * tig + 1) * 68 + cc];
                unsigned t2 = sB[(kb + 8 + 2 * tig)     * 68 + cc];
                unsigned t3 = sB[(kb + 8 + 2 * tig + 1) * 68 + cc];
                unsigned bh[2], bl[2];
                bh[0] = __byte_perm(t0, t1, 0x7632);
                bl[0] = __byte_perm(t0, t1, 0x5410);
                bh[1] = __byte_perm(t2, t3, 0x7632);
                bl[1] = __byte_perm(t2, t3, 0x5410);
#pragma unroll
                for (int mt = 0; mt < 2; mt++) {
                    mma_bf16(acc[mt][nt], ah[mt], bh);
                    mma_bf16(acc[mt][nt], ah[mt], bl);
                    mma_bf16(acc[mt][nt], al[mt], bh);
                }
            }
        }
    }

    // epilogue: bias + leakyrelu (+ residual write for layer 2)
#pragma unroll
    for (int mt = 0; mt < 2; mt++) {
#pragma unroll
        for (int half = 0; half < 2; half++) {
            int row = bm + wm + mt * 16 + g + half * 8;
            if (row >= N_NODES) continue;
#pragma unroll
            for (int nt = 0; nt < 4; nt++) {
                int col = wn + nt * 8 + tig * 2;
                float v0 = acc[mt][nt][2 * half]     + sBias[col];
                float v1 = acc[mt][nt][2 * half + 1] + sBias[col + 1];
                float2 o;
                o.x = v0 > 0.f ? v0 : 0.01f * v0;
                o.y = v1 > 0.f ? v1 : 0.01f * v1;
                *reinterpret_cast<float2*>(C + (size_t)row * 64 + col) = o;
                if (resid_out) {
                    float2 r2 = *reinterpret_cast<const float2*>(
                                    resid_in + (size_t)row * 64 + col);
                    float2 q;
                    q.x = o.x + r2.x;
                    q.y = o.y + r2.y;
                    *reinterpret_cast<float2*>(resid_out + (size_t)row * 64 + col) = q;
                }
            }
        }
    }
}

// -------------------- pooling ----------------------------------------------
__global__ void k_pool(const int* __restrict__ batch) {
    int f = threadIdx.x;
    int n0 = blockIdx.x * 64;
    int n1 = min(n0 + 64, N_NODES);
    const float* base = (f < 64) ? g_x4 : (f < 128) ? g_x1 : (f < 192) ? g_x2 : g_x3;
    int fo = f & 63;
    float m = -FLT_MAX;
    int cur = -1;
    for (int n = n0; n < n1; n++) {
        int b = batch[n];
        if (b != cur) {
            if (cur >= 0) atomicMax(&g_pmax[cur * 256 + f], fenc(m));
            cur = b;
            m = -FLT_MAX;
        }
        m = fmaxf(m, base[(size_t)n * 64 + fo]);
    }
    if (cur >= 0) atomicMax(&g_pmax[cur * 256 + f], fenc(m));
}

// -------------------- final MLP --------------------------------------------
__global__ void k_mlp(const float* __restrict__ w1, const float* __restrict__ b1,
                      const float* __restrict__ gamma, const float* __restrict__ beta,
                      const float* __restrict__ w2, const float* __restrict__ b2,
                      float* __restrict__ out) {
    int g = blockIdx.x;
    int t = threadIdx.x;
    __shared__ float sp[256];
    __shared__ float sz[64];
    for (int i = t; i < 256; i += 64) sp[i] = fdec(g_pmax[g * 256 + i]);
    __syncthreads();
    float acc = b1[t];
    for (int j = 0; j < 256; j++) acc = fmaf(sp[j], w1[j * 64 + t], acc);
    const float invs = 0.99999500003749969f;   // 1/sqrt(1 + 1e-5)
    acc = acc * invs * gamma[t] + beta[t];
    acc = fmaxf(acc, 0.f);
    sz[t] = acc;
    __syncthreads();
    if (t < 10) {
        float o = b2[t];
        for (int j = 0; j < 64; j++) o = fmaf(sz[j], w2[j * 10 + t], o);
        out[g * 10 + t] = o;
    }
}

// -------------------- host launch ------------------------------------------
extern "C" void kernel_launch(void* const* d_in, const int* in_sizes, int n_in,
                              void* d_out, int out_size) {
    (void)in_sizes; (void)n_in; (void)out_size;

    const float* x     = (const float*)d_in[0];
    const int*   ei    = (const int*)d_in[1];
    const int*   batch = (const int*)d_in[2];
    const float* ea    = (const float*)d_in[3];
    const float* g_w[4]   = {(const float*)d_in[4],  (const float*)d_in[9],
                             (const float*)d_in[14], (const float*)d_in[19]};
    const float* mu_w[4]  = {(const float*)d_in[5],  (const float*)d_in[10],
                             (const float*)d_in[15], (const float*)d_in[20]};
    const float* sig_w[4] = {(const float*)d_in[6],  (const float*)d_in[11],
                             (const float*)d_in[16], (const float*)d_in[21]};
    const float* rw_w[4]  = {(const float*)d_in[7],  (const float*)d_in[12],
                             (const float*)d_in[17], (const float*)d_in[22]};
    const float* b_w[4]   = {(const float*)d_in[8],  (const float*)d_in[13],
                             (const float*)d_in[18], (const float*)d_in[23]};
    const float* w1    = (const float*)d_in[24];
    const float* b1    = (const float*)d_in[25];
    const float* gamma = (const float*)d_in[26];
    const float* beta  = (const float*)d_in[27];
    const float* w2    = (const float*)d_in[28];
    const float* b2    = (const float*)d_in[29];

    float *p_x0, *p_x1, *p_x2, *p_x3, *p_x4;
    unsigned* p_Bp;
    float* p_gw;
    cudaGetSymbolAddress((void**)&p_x0, g_x0);
    cudaGetSymbolAddress((void**)&p_x1, g_x1);
    cudaGetSymbolAddress((void**)&p_x2, g_x2);
    cudaGetSymbolAddress((void**)&p_x3, g_x3);
    cudaGetSymbolAddress((void**)&p_x4, g_x4);
    cudaGetSymbolAddress((void**)&p_Bp, g_Bp);
    cudaGetSymbolAddress((void**)&p_gw, g_gwall);

    const int EB = (N_EDGES + 255) / 256;   // 3125

    k_setup<<<(SETUP_MAX + 255) / 256, 256>>>(g_w[0], rw_w[0], g_w[1], rw_w[1],
                                              g_w[2], rw_w[2], g_w[3], rw_w[3]);
    k_hist<<<EB, 256>>>(ei);
    k_scan_part<<<NBLK_SCAN, 256>>>();
    k_scan_final<<<NBLK_SCAN, 256>>>();
    k_scatter<<<EB, 256>>>(ei, ea);
    k_gw_all<<<EB, 256>>>(mu_w[0], sig_w[0], mu_w[1], sig_w[1],
                          mu_w[2], sig_w[2], mu_w[3], sig_w[3]);

    const int agg_blocks  = (N_NODES * 32 + 255) / 256;
    const int gemm_blocks = (N_NODES + 127) / 128;   // 391

    const float* layer_in[4]  = {x, p_x0, p_x1, p_x3};
    float*       layer_out[4] = {p_x0, p_x1, p_x2, p_x4};

    for (int l = 0; l < 4; l++) {
        const float* rin  = (l == 2) ? p_x0 : nullptr;
        float*       rout = (l == 2) ? p_x3 : nullptr;
        k_aggY<<<agg_blocks, 256>>>(layer_in[l], p_gw + (size_t)l * N_EDGES * 4);
        k_gemm<<<gemm_blocks, 256>>>(p_Bp + (size_t)l * KY * H, b_w[l],
                                     layer_out[l], rin, rout);
    }

    k_pool<<<(N_NODES + 63) / 64, 256>>>(batch);
    k_mlp<<<G_GRAPHS, 64>>>(w1, b1, gamma, beta, w2, b2, (float*)d_out);
}